// round 6
// baseline (speedup 1.0000x reference)
#include <cuda_runtime.h>

// AOLayer: out[b,n,a] = ang * rad, B=512,N=32,A=256,P=6.
// Round 6: MUFU pipe measured ~95% busy (21.2K of 22.2K cyc across r1-r5,
// invariant to instruction mix). Rebalance: 4 exps stay on MUFU (ex2.approx),
// 2 exps move to an FMA-pipe polynomial exp2 (range reduction + deg-4 Taylor).
// New bound: max(MUFU 64, FMA 72) vs old 96 cyc/row/warp -> ~1.3x.

#define A_DIM 256
#define P_DIM 6
#define BN_DIM (512 * 32)
#define ROWS_PER_BLOCK 16

__device__ __forceinline__ float ex2f(float x) {
    float r;
    asm("ex2.approx.f32 %0, %1;" : "=f"(r) : "f"(x));
    return r;
}

// rad += co * 2^(ep*r2)  computed entirely on FMA/ALU pipes (no MUFU).
// Valid for ep*r2 <= 0 (args down to ~-1e4; clamped at 2^-126 -> abs err <=1e-29).
__device__ __forceinline__ void exp2_poly_acc(float ep, float r2, float co, float& rad) {
    // round(x) via magic number: t = x + 1.5*2^23, x in [-870, 0] keeps t in [2^23, 2^24)
    const float MAGIC = 12582912.0f;  // 1.5 * 2^23
    float t = fmaf(ep, r2, MAGIC);                 // FFMA
    int ti = __float_as_int(t);
    ti = max(ti, 0x4B3FFF82);                      // IMNMX (alu): clamp n >= -126
    // scale = 2^n : (ti * 2^23) mod 2^32 = n<<23 (low 9 bits of 0x4B400000 are 0)
    float scale = __int_as_float((int)((unsigned)ti * 0x800000u + 0x3F800000u)); // IMAD
    float nf = __int_as_float(ti) - MAGIC;         // FADD: clamped n as float
    float f = fmaf(ep, r2, -nf);                   // FFMA: frac in [-0.5, 0.5]
    // 2^f, degree-4 Taylor in ln2 (rel err ~4e-5 on [-0.5,0.5])
    float p = 0.009618129f;
    p = fmaf(p, f, 0.05550411f);
    p = fmaf(p, f, 0.2402265f);
    p = fmaf(p, f, 0.6931472f);
    p = fmaf(p, f, 1.0f);
    rad = fmaf(co * scale, p, rad);                // FMUL + FFMA
}

__global__ void __launch_bounds__(A_DIM) aolayer_kernel(
    const float* __restrict__ pos,      // [BN, 3]
    const float* __restrict__ centers,  // [A, 3]
    const float* __restrict__ exps,     // [A, P]
    const float* __restrict__ coeffs,   // [A, P]
    const int*   __restrict__ powers,   // [A, 3]
    float* __restrict__ out)            // [BN, A]
{
    const int a = threadIdx.x;

    // ---- per-atom constants (once per block) ----
    const float ncx = -centers[a * 3 + 0];
    const float ncy = -centers[a * 3 + 1];
    const float ncz = -centers[a * 3 + 2];

    const float NEG_LOG2E = -1.4426950408889634f;
    float ep[P_DIM], co[P_DIM];
#pragma unroll
    for (int p = 0; p < P_DIM; p++) {
        ep[p] = exps[a * P_DIM + p] * NEG_LOG2E;
        co[p] = coeffs[a * P_DIM + p];
    }

    const int px = powers[a * 3 + 0];
    const int py = powers[a * 3 + 1];
    const int pz = powers[a * 3 + 2];
    const bool lx = (px >= 1), qx = (px == 2);
    const bool ly = (py >= 1), qy = (py == 2);
    const bool lz = (pz >= 1), qz = (pz == 2);

    // ---- stage pos rows into shared memory ----
    __shared__ float spos[ROWS_PER_BLOCK * 3];
    const int row0 = blockIdx.x * ROWS_PER_BLOCK;
    if (threadIdx.x < ROWS_PER_BLOCK * 3) {
        spos[threadIdx.x] = pos[row0 * 3 + threadIdx.x];
    }
    __syncthreads();

    float* out_base = out + (size_t)row0 * A_DIM + a;

#pragma unroll
    for (int r = 0; r < ROWS_PER_BLOCK; r++) {
        const float dx = spos[r * 3 + 0] + ncx;
        const float dy = spos[r * 3 + 1] + ncy;
        const float dz = spos[r * 3 + 2] + ncz;

        const float r2 = fmaf(dx, dx, fmaf(dy, dy, dz * dz));

        // 4 exps on MUFU, 2 on the FMA-pipe polynomial; dual accumulators
        float rad0 = co[0] * ex2f(ep[0] * r2);
        float rad1 = co[1] * ex2f(ep[1] * r2);
        rad0 = fmaf(co[2], ex2f(ep[2] * r2), rad0);
        rad1 = fmaf(co[3], ex2f(ep[3] * r2), rad1);
        exp2_poly_acc(ep[4], r2, co[4], rad0);
        exp2_poly_acc(ep[5], r2, co[5], rad1);

        float o = rad0 + rad1;

        // angular folded in as predicated muls (predicates loop-invariant)
        if (lx) o *= dx;
        if (qx) o *= dx;
        if (ly) o *= dy;
        if (qy) o *= dy;
        if (lz) o *= dz;
        if (qz) o *= dz;

        out_base[r * A_DIM] = o;
    }
}

extern "C" void kernel_launch(void* const* d_in, const int* in_sizes, int n_in,
                              void* d_out, int out_size) {
    const float* pos     = (const float*)d_in[0];
    const float* centers = (const float*)d_in[1];
    const float* exps    = (const float*)d_in[2];
    const float* coeffs  = (const float*)d_in[3];
    const int*   powers  = (const int*)d_in[4];
    float* out = (float*)d_out;

    dim3 grid(BN_DIM / ROWS_PER_BLOCK);  // 1024 blocks
    dim3 block(A_DIM);                   // 256 threads, one per atom
    aolayer_kernel<<<grid, block>>>(pos, centers, exps, coeffs, powers, out);
}

// round 7
// speedup vs baseline: 1.1400x; 1.1400x over previous
#include <cuda_runtime.h>

// AOLayer: out[b,n,a] = ang * rad, B=512,N=32,A=256,P=6.
// Round 7: single-wave residency. All prior rounds ran 1024 blocks at
// 6/SM (regs=40) -> 2 waves with a 136-block straggler tail; instruction-mix
// changes had elasticity ~0.2 because the tail dominates. Force 7 blocks/SM
// (regs<=36) via __launch_bounds__(256,7); angular product computed early to
// shrink live ranges so 36 regs fits without spills.

#define A_DIM 256
#define P_DIM 6
#define BN_DIM (512 * 32)
#define ROWS_PER_BLOCK 16

__device__ __forceinline__ float ex2f(float x) {
    float r;
    asm("ex2.approx.f32 %0, %1;" : "=f"(r) : "f"(x));
    return r;
}

__global__ void __launch_bounds__(A_DIM, 7) aolayer_kernel(
    const float* __restrict__ pos,      // [BN, 3]
    const float* __restrict__ centers,  // [A, 3]
    const float* __restrict__ exps,     // [A, P]
    const float* __restrict__ coeffs,   // [A, P]
    const int*   __restrict__ powers,   // [A, 3]
    float* __restrict__ out)            // [BN, A]
{
    const int a = threadIdx.x;

    // ---- per-atom constants (once per block) ----
    const float ncx = -centers[a * 3 + 0];
    const float ncy = -centers[a * 3 + 1];
    const float ncz = -centers[a * 3 + 2];

    const float NEG_LOG2E = -1.4426950408889634f;
    float ep[P_DIM], co[P_DIM];
#pragma unroll
    for (int p = 0; p < P_DIM; p++) {
        ep[p] = exps[a * P_DIM + p] * NEG_LOG2E;
        co[p] = coeffs[a * P_DIM + p];
    }

    const int px = powers[a * 3 + 0];
    const int py = powers[a * 3 + 1];
    const int pz = powers[a * 3 + 2];
    // loop-invariant predicates -> ISETPs hoisted out of the unrolled loop
    const bool lx = (px >= 1), qx = (px == 2);
    const bool ly = (py >= 1), qy = (py == 2);
    const bool lz = (pz >= 1), qz = (pz == 2);

    // ---- stage pos rows into shared memory ----
    __shared__ float spos[ROWS_PER_BLOCK * 3];
    const int row0 = blockIdx.x * ROWS_PER_BLOCK;
    if (threadIdx.x < ROWS_PER_BLOCK * 3) {
        spos[threadIdx.x] = pos[row0 * 3 + threadIdx.x];
    }
    __syncthreads();

    float* out_base = out + (size_t)row0 * A_DIM + a;

#pragma unroll
    for (int r = 0; r < ROWS_PER_BLOCK; r++) {
        const float dx = spos[r * 3 + 0] + ncx;
        const float dy = spos[r * 3 + 1] + ncy;
        const float dz = spos[r * 3 + 2] + ncz;

        const float r2 = fmaf(dx, dx, fmaf(dy, dy, dz * dz));

        // angular FIRST so dx/dy/dz die before the EX2 region (reg pressure)
        float ang = lx ? dx : 1.0f;
        if (qx) ang *= dx;
        if (ly) ang *= dy;
        if (qy) ang *= dy;
        if (lz) ang *= dz;
        if (qz) ang *= dz;

        // radial: dual accumulators, 6 MUFU ex2
        float rad0 = co[0] * ex2f(ep[0] * r2);
        float rad1 = co[1] * ex2f(ep[1] * r2);
        rad0 = fmaf(co[2], ex2f(ep[2] * r2), rad0);
        rad1 = fmaf(co[3], ex2f(ep[3] * r2), rad1);
        rad0 = fmaf(co[4], ex2f(ep[4] * r2), rad0);
        rad1 = fmaf(co[5], ex2f(ep[5] * r2), rad1);

        out_base[r * A_DIM] = ang * (rad0 + rad1);
    }
}

extern "C" void kernel_launch(void* const* d_in, const int* in_sizes, int n_in,
                              void* d_out, int out_size) {
    const float* pos     = (const float*)d_in[0];
    const float* centers = (const float*)d_in[1];
    const float* exps    = (const float*)d_in[2];
    const float* coeffs  = (const float*)d_in[3];
    const int*   powers  = (const int*)d_in[4];
    float* out = (float*)d_out;

    dim3 grid(BN_DIM / ROWS_PER_BLOCK);  // 1024 blocks -> 7/SM, single wave
    dim3 block(A_DIM);                   // 256 threads, one per atom
    aolayer_kernel<<<grid, block>>>(pos, centers, exps, coeffs, powers, out);
}